// round 2
// baseline (speedup 1.0000x reference)
#include <cuda_runtime.h>
#include <cuda_bf16.h>
#include <math.h>

// ---------------- problem constants ----------------
#define BATCH 16
#define HW    56
#define CH    384
#define NHEAD 12
#define WS    7
#define NTOK  49              // WS*WS
#define HD    32              // CH/NHEAD
#define NWIN  64              // per image
#define MROWS 50176           // BATCH*HW*HW
#define HID   1536
#define SCALE 0.17677669529663687f   // 32^-0.5

// ---------------- scratch (static device memory; no allocations) -----------
__device__ float g_qkv[(long)MROWS * 3 * CH];     // 231 MB
__device__ float g_attn[(long)MROWS * CH];        // 77 MB
__device__ float g_x2[(long)MROWS * CH];          // 77 MB
__device__ float g_hn[(long)MROWS * CH];          // 77 MB
__device__ float g_hidden[(long)MROWS * HID];     // 308 MB
__device__ int   g_map[MROWS];

// ---------------- row permutation (shift + window partition) ---------------
// windowed row r = (b*64 + wi*8 + wj)*49 + ti*7 + tj  maps to image row
// b*3136 + ((wi*7+ti+3)%56)*56 + ((wj*7+tj+3)%56)
__global__ void build_maps_kernel(int* __restrict__ map) {
    int r = blockIdx.x * 256 + threadIdx.x;
    if (r >= MROWS) return;
    int w = r / NTOK, t = r % NTOK;
    int b = w / NWIN, wrem = w % NWIN;
    int wi = wrem / 8, wj = wrem % 8;
    int ti = t / WS, tj = t % WS;
    int h0 = (wi * WS + ti + 3) % HW;
    int w0 = (wj * WS + tj + 3) % HW;
    map[r] = b * (HW * HW) + h0 * HW + w0;
}

// ---------------- tiled SGEMM: C[M,N] = A[M,K] @ W[N,K]^T + bias ----------
// EPI: 0 = none, 1 = exact GELU, 2 = += resid
#define BM 128
#define BN 128
#define BKK 8

template <int EPI>
__global__ __launch_bounds__(256)
void gemm_bias(const float* __restrict__ A, const float* __restrict__ W,
               const float* __restrict__ bias, float* __restrict__ C,
               int M, int N, int K,
               const int* __restrict__ a_map, const int* __restrict__ c_map,
               const float* __restrict__ resid)
{
    __shared__ float As[BKK][BM];
    __shared__ float Bs[BKK][BN];

    int tid = threadIdx.x;
    int bm = blockIdx.y * BM;
    int bn = blockIdx.x * BN;
    int tx = tid & 15, ty = tid >> 4;

    int lr = tid >> 1;            // row within tile (0..127)
    int lk = (tid & 1) * 4;       // k offset (0 or 4)

    long arow = a_map ? (long)a_map[bm + lr] : (long)(bm + lr);
    const float* Ar = A + arow * K;
    const float* Wr = W + (long)(bn + lr) * K;

    float acc[8][8];
    #pragma unroll
    for (int i = 0; i < 8; i++)
        #pragma unroll
        for (int j = 0; j < 8; j++) acc[i][j] = 0.0f;

    for (int k0 = 0; k0 < K; k0 += BKK) {
        float4 av = *(const float4*)(Ar + k0 + lk);
        float4 bv = *(const float4*)(Wr + k0 + lk);
        As[lk + 0][lr] = av.x; As[lk + 1][lr] = av.y;
        As[lk + 2][lr] = av.z; As[lk + 3][lr] = av.w;
        Bs[lk + 0][lr] = bv.x; Bs[lk + 1][lr] = bv.y;
        Bs[lk + 2][lr] = bv.z; Bs[lk + 3][lr] = bv.w;
        __syncthreads();
        #pragma unroll
        for (int kk = 0; kk < BKK; kk++) {
            float a[8], b[8];
            *(float4*)(a)     = *(const float4*)&As[kk][ty * 8];
            *(float4*)(a + 4) = *(const float4*)&As[kk][ty * 8 + 4];
            *(float4*)(b)     = *(const float4*)&Bs[kk][tx * 8];
            *(float4*)(b + 4) = *(const float4*)&Bs[kk][tx * 8 + 4];
            #pragma unroll
            for (int i = 0; i < 8; i++)
                #pragma unroll
                for (int j = 0; j < 8; j++)
                    acc[i][j] += a[i] * b[j];
        }
        __syncthreads();
    }

    #pragma unroll
    for (int i = 0; i < 8; i++) {
        int gm = bm + ty * 8 + i;
        long orow = c_map ? (long)c_map[gm] : (long)gm;
        #pragma unroll
        for (int j = 0; j < 8; j++) {
            int gn = bn + tx * 8 + j;
            float v = acc[i][j] + bias[gn];
            if (EPI == 1) {
                v = 0.5f * v * (1.0f + erff(v * 0.70710678118654752f));
            } else if (EPI == 2) {
                v += resid[orow * N + gn];
            }
            C[orow * N + gn] = v;
        }
    }
}

// ---------------- windowed attention: one block per (window, head) ---------
__global__ __launch_bounds__(256)
void attn_kernel(const float* __restrict__ qkv, const float* __restrict__ mask,
                 const float* __restrict__ rpb, float* __restrict__ out)
{
    int w = blockIdx.x;   // 0..1023
    int h = blockIdx.y;   // 0..11

    __shared__ float q[NTOK][HD];
    __shared__ float k[NTOK][HD];
    __shared__ float v[NTOK][HD];
    __shared__ float s[NTOK][52];

    int tid = threadIdx.x;
    const float* base = qkv + (long)w * NTOK * (3 * CH) + h * HD;

    for (int idx = tid; idx < NTOK * HD; idx += 256) {
        int t = idx >> 5, d = idx & 31;
        const float* row = base + (long)t * (3 * CH) + d;
        q[t][d] = row[0] * SCALE;
        k[t][d] = row[CH];
        v[t][d] = row[2 * CH];
    }
    __syncthreads();

    int wimg = w & (NWIN - 1);
    const float* mrow = mask + (long)wimg * NTOK * NTOK;
    for (int idx = tid; idx < NTOK * NTOK; idx += 256) {
        int t1 = idx / NTOK, t2 = idx % NTOK;
        float acc = 0.0f;
        #pragma unroll
        for (int d = 0; d < HD; d++) acc += q[t1][d] * k[t2][d];
        int di = (t1 / WS) - (t2 / WS) + (WS - 1);
        int dj = (t1 % WS) - (t2 % WS) + (WS - 1);
        acc += rpb[(di * (2 * WS - 1) + dj) * NHEAD + h];
        acc += mrow[idx];
        s[t1][t2] = acc;
    }
    __syncthreads();

    if (tid < NTOK) {
        float mx = -1e30f;
        #pragma unroll
        for (int j = 0; j < NTOK; j++) mx = fmaxf(mx, s[tid][j]);
        float sum = 0.0f;
        #pragma unroll
        for (int j = 0; j < NTOK; j++) {
            float e = __expf(s[tid][j] - mx);
            s[tid][j] = e;
            sum += e;
        }
        float inv = 1.0f / sum;
        #pragma unroll
        for (int j = 0; j < NTOK; j++) s[tid][j] *= inv;
    }
    __syncthreads();

    float* obase = out + (long)w * NTOK * CH + h * HD;
    for (int idx = tid; idx < NTOK * HD; idx += 256) {
        int t = idx >> 5, d = idx & 31;
        float acc = 0.0f;
        #pragma unroll
        for (int m = 0; m < NTOK; m++) acc += s[t][m] * v[m][d];
        obase[(long)t * CH + d] = acc;
    }
}

// ---------------- LayerNorm over C=384, one block (128 thr) per row --------
__global__ __launch_bounds__(128)
void ln_kernel(const float* __restrict__ x, const float* __restrict__ g,
               const float* __restrict__ b, float* __restrict__ o)
{
    long row = blockIdx.x;
    const float* xr = x + row * CH;
    int tid = threadIdx.x;

    float v0 = xr[tid], v1 = xr[tid + 128], v2 = xr[tid + 256];
    float sum = v0 + v1 + v2;

    __shared__ float red1[4];
    __shared__ float red2[4];
    #pragma unroll
    for (int off = 16; off; off >>= 1) sum += __shfl_xor_sync(0xffffffff, sum, off);
    if ((tid & 31) == 0) red1[tid >> 5] = sum;
    __syncthreads();
    float mu = (red1[0] + red1[1] + red1[2] + red1[3]) * (1.0f / CH);

    float d0 = v0 - mu, d1 = v1 - mu, d2 = v2 - mu;
    float sq = d0 * d0 + d1 * d1 + d2 * d2;
    #pragma unroll
    for (int off = 16; off; off >>= 1) sq += __shfl_xor_sync(0xffffffff, sq, off);
    if ((tid & 31) == 0) red2[tid >> 5] = sq;
    __syncthreads();
    float var = (red2[0] + red2[1] + red2[2] + red2[3]) * (1.0f / CH);
    float rstd = rsqrtf(var + 1e-5f);

    float* orow = o + row * CH;
    orow[tid]       = d0 * rstd * g[tid]       + b[tid];
    orow[tid + 128] = d1 * rstd * g[tid + 128] + b[tid + 128];
    orow[tid + 256] = d2 * rstd * g[tid + 256] + b[tid + 256];
}

// ---------------- launch ----------------------------------------------------
extern "C" void kernel_launch(void* const* d_in, const int* in_sizes, int n_in,
                              void* d_out, int out_size)
{
    const float* x      = (const float*)d_in[0];
    const float* mask   = (const float*)d_in[1];
    const float* qkv_w  = (const float*)d_in[2];
    const float* qkv_b  = (const float*)d_in[3];
    const float* proj_w = (const float*)d_in[4];
    const float* proj_b = (const float*)d_in[5];
    const float* rpb    = (const float*)d_in[6];
    const float* n2g    = (const float*)d_in[7];
    const float* n2b    = (const float*)d_in[8];
    const float* fc1w   = (const float*)d_in[9];
    const float* fc1b   = (const float*)d_in[10];
    const float* fc2w   = (const float*)d_in[11];
    const float* fc2b   = (const float*)d_in[12];
    float* out = (float*)d_out;

    void *p_qkv, *p_attn, *p_x2, *p_hn, *p_hidden, *p_map;
    cudaGetSymbolAddress(&p_qkv, g_qkv);
    cudaGetSymbolAddress(&p_attn, g_attn);
    cudaGetSymbolAddress(&p_x2, g_x2);
    cudaGetSymbolAddress(&p_hn, g_hn);
    cudaGetSymbolAddress(&p_hidden, g_hidden);
    cudaGetSymbolAddress(&p_map, g_map);
    float* qkv    = (float*)p_qkv;
    float* attn   = (float*)p_attn;
    float* x2     = (float*)p_x2;
    float* hn     = (float*)p_hn;
    float* hidden = (float*)p_hidden;
    int*   map    = (int*)p_map;

    build_maps_kernel<<<(MROWS + 255) / 256, 256>>>(map);

    // QKV: gather rows of x through shift/window map
    gemm_bias<0><<<dim3((3 * CH) / BN, MROWS / BM), 256>>>(
        x, qkv_w, qkv_b, qkv, MROWS, 3 * CH, CH, map, nullptr, nullptr);

    // windowed attention
    attn_kernel<<<dim3(BATCH * NWIN, NHEAD), 256>>>(qkv, mask, rpb, attn);

    // proj + scatter back to image layout -> x2
    gemm_bias<0><<<dim3(CH / BN, MROWS / BM), 256>>>(
        attn, proj_w, proj_b, x2, MROWS, CH, CH, nullptr, map, nullptr);

    // LayerNorm(x2) -> hn
    ln_kernel<<<MROWS, 128>>>(x2, n2g, n2b, hn);

    // FC1 + exact GELU
    gemm_bias<1><<<dim3(HID / BN, MROWS / BM), 256>>>(
        hn, fc1w, fc1b, hidden, MROWS, HID, CH, nullptr, nullptr, nullptr);

    // FC2 + residual(x2) -> out
    gemm_bias<2><<<dim3(CH / BN, MROWS / BM), 256>>>(
        hidden, fc2w, fc2b, out, MROWS, CH, HID, nullptr, nullptr, x2);
}

// round 3
// speedup vs baseline: 1.4844x; 1.4844x over previous
#include <cuda_runtime.h>
#include <cuda_bf16.h>
#include <math.h>
#include <stdint.h>

// ---------------- problem constants ----------------
#define BATCH 16
#define HW    56
#define CH    384
#define NHEAD 12
#define WS    7
#define NTOK  49
#define HD    32
#define NWIN  64
#define MROWS 50176
#define HID   1536
#define SCALE 0.17677669529663687f

// ---------------- scratch ----------------
__device__ __nv_bfloat16 g_xg_hi[(long)MROWS * CH];
__device__ __nv_bfloat16 g_xg_lo[(long)MROWS * CH];
__device__ float         g_qkv[(long)MROWS * 3 * CH];      // fp32, windowed order
__device__ __nv_bfloat16 g_at_hi[(long)MROWS * CH];
__device__ __nv_bfloat16 g_at_lo[(long)MROWS * CH];
__device__ float         g_x2[(long)MROWS * CH];
__device__ __nv_bfloat16 g_hn_hi[(long)MROWS * CH];
__device__ __nv_bfloat16 g_hn_lo[(long)MROWS * CH];
__device__ __nv_bfloat16 g_hid_hi[(long)MROWS * HID];
__device__ __nv_bfloat16 g_hid_lo[(long)MROWS * HID];
__device__ int g_map[MROWS];
// weight splits
__device__ __nv_bfloat16 g_wqkv_hi[3 * CH * CH], g_wqkv_lo[3 * CH * CH];
__device__ __nv_bfloat16 g_wprj_hi[CH * CH],     g_wprj_lo[CH * CH];
__device__ __nv_bfloat16 g_wf1_hi[HID * CH],     g_wf1_lo[HID * CH];
__device__ __nv_bfloat16 g_wf2_hi[CH * HID],     g_wf2_lo[CH * HID];

// ---------------- row permutation map ----------------
__global__ void build_maps_kernel(int* __restrict__ map) {
    int r = blockIdx.x * 256 + threadIdx.x;
    if (r >= MROWS) return;
    int w = r / NTOK, t = r % NTOK;
    int b = w / NWIN, wrem = w % NWIN;
    int wi = wrem / 8, wj = wrem % 8;
    int ti = t / WS, tj = t % WS;
    int h0 = (wi * WS + ti + 3) % HW;
    int w0 = (wj * WS + tj + 3) % HW;
    map[r] = b * (HW * HW) + h0 * HW + w0;
}

// ---------------- fp32 -> bf16 hi/lo split ----------------
__device__ __forceinline__ void split_bf16(float v, __nv_bfloat16& h, __nv_bfloat16& l) {
    h = __float2bfloat16(v);
    l = __float2bfloat16(v - __bfloat162float(h));
}

__global__ void conv_split(const float* __restrict__ src,
                           __nv_bfloat16* __restrict__ hi, __nv_bfloat16* __restrict__ lo,
                           long n) {
    long i = (long)blockIdx.x * 256 + threadIdx.x;
    if (i >= n) return;
    __nv_bfloat16 h, l;
    split_bf16(src[i], h, l);
    hi[i] = h; lo[i] = l;
}

__global__ void conv_gather_split(const float* __restrict__ x, const int* __restrict__ map,
                                  __nv_bfloat16* __restrict__ hi, __nv_bfloat16* __restrict__ lo) {
    long i = (long)blockIdx.x * 256 + threadIdx.x;
    if (i >= (long)MROWS * CH) return;
    long r = i / CH, c = i % CH;
    float v = x[(long)map[r] * CH + c];
    __nv_bfloat16 h, l;
    split_bf16(v, h, l);
    hi[i] = h; lo[i] = l;
}

// ---------------- bf16x3 tensor-core GEMM ----------------
// C[M,N] = A[M,K] @ W[N,K]^T + bias, A/W split hi+lo, 3 MMA products.
// Tile 128x64xBK32, 8 warps (4M x 2N), warp tile 32x32 (2x4 m16n8k16 frags).
// EPI: 0 = fp32 out, 1 = fp32 scatter via c_map, 2 = GELU -> bf16 hi/lo out,
//      3 = +resid -> fp32 out

__device__ __forceinline__ void mma16816(float* c, const uint32_t* a, uint32_t b0, uint32_t b1) {
    asm volatile(
        "mma.sync.aligned.m16n8k16.row.col.f32.bf16.bf16.f32 "
        "{%0,%1,%2,%3}, {%4,%5,%6,%7}, {%8,%9}, {%0,%1,%2,%3};\n"
        : "+f"(c[0]), "+f"(c[1]), "+f"(c[2]), "+f"(c[3])
        : "r"(a[0]), "r"(a[1]), "r"(a[2]), "r"(a[3]), "r"(b0), "r"(b1));
}

#define SAST 20   // smem row stride in u32 (40 bf16) -> conflict-free frag loads

template <int EPI>
__global__ __launch_bounds__(256, 2)
void gemm_mma(const __nv_bfloat16* __restrict__ Ahi, const __nv_bfloat16* __restrict__ Alo,
              const __nv_bfloat16* __restrict__ Bhi, const __nv_bfloat16* __restrict__ Blo,
              const float* __restrict__ bias,
              float* __restrict__ Cf,
              __nv_bfloat16* __restrict__ Chi, __nv_bfloat16* __restrict__ Clo,
              int M, int N, int K,
              const int* __restrict__ c_map, const float* __restrict__ resid)
{
    __shared__ __align__(16) uint32_t sAhi[128][SAST];
    __shared__ __align__(16) uint32_t sAlo[128][SAST];
    __shared__ __align__(16) uint32_t sBhi[64][SAST];
    __shared__ __align__(16) uint32_t sBlo[64][SAST];

    int tid = threadIdx.x;
    int bm = blockIdx.y * 128, bn = blockIdx.x * 64;
    int warp = tid >> 5, lane = tid & 31;
    int warpM = warp & 3, warpN = warp >> 2;
    int grp = lane >> 2, tig = lane & 3;

    float acc[2][4][4];
    #pragma unroll
    for (int a = 0; a < 2; a++)
        #pragma unroll
        for (int b = 0; b < 4; b++)
            #pragma unroll
            for (int c = 0; c < 4; c++) acc[a][b][c] = 0.0f;

    int lrow = tid >> 2;          // 0..63
    int lcu = (tid & 3) * 4;      // u32 col in smem
    int lce = (tid & 3) * 8;      // bf16 col in gmem

    const __nv_bfloat16* pAh = Ahi + (size_t)(bm + lrow) * K + lce;
    const __nv_bfloat16* pAl = Alo + (size_t)(bm + lrow) * K + lce;
    const __nv_bfloat16* pBh = Bhi + (size_t)(bn + lrow) * K + lce;
    const __nv_bfloat16* pBl = Blo + (size_t)(bn + lrow) * K + lce;
    size_t rowoff64 = (size_t)64 * K;

    for (int k0 = 0; k0 < K; k0 += 32) {
        uint4 ah0 = *(const uint4*)(pAh + k0);
        uint4 ah1 = *(const uint4*)(pAh + k0 + rowoff64);
        uint4 al0 = *(const uint4*)(pAl + k0);
        uint4 al1 = *(const uint4*)(pAl + k0 + rowoff64);
        uint4 bh0 = *(const uint4*)(pBh + k0);
        uint4 bl0 = *(const uint4*)(pBl + k0);

        *(uint4*)&sAhi[lrow][lcu]      = ah0;
        *(uint4*)&sAhi[lrow + 64][lcu] = ah1;
        *(uint4*)&sAlo[lrow][lcu]      = al0;
        *(uint4*)&sAlo[lrow + 64][lcu] = al1;
        *(uint4*)&sBhi[lrow][lcu]      = bh0;
        *(uint4*)&sBlo[lrow][lcu]      = bl0;
        __syncthreads();

        #pragma unroll
        for (int ks = 0; ks < 2; ks++) {
            int kc = ks * 8;
            uint32_t ah[2][4], al[2][4];
            #pragma unroll
            for (int mi = 0; mi < 2; mi++) {
                int r = warpM * 32 + mi * 16;
                ah[mi][0] = sAhi[r + grp][kc + tig];
                ah[mi][1] = sAhi[r + grp + 8][kc + tig];
                ah[mi][2] = sAhi[r + grp][kc + tig + 4];
                ah[mi][3] = sAhi[r + grp + 8][kc + tig + 4];
                al[mi][0] = sAlo[r + grp][kc + tig];
                al[mi][1] = sAlo[r + grp + 8][kc + tig];
                al[mi][2] = sAlo[r + grp][kc + tig + 4];
                al[mi][3] = sAlo[r + grp + 8][kc + tig + 4];
            }
            #pragma unroll
            for (int ni = 0; ni < 4; ni++) {
                int c = warpN * 32 + ni * 8;
                uint32_t b0h = sBhi[c + grp][kc + tig];
                uint32_t b1h = sBhi[c + grp][kc + tig + 4];
                uint32_t b0l = sBlo[c + grp][kc + tig];
                uint32_t b1l = sBlo[c + grp][kc + tig + 4];
                #pragma unroll
                for (int mi = 0; mi < 2; mi++) {
                    mma16816(acc[mi][ni], ah[mi], b0h, b1h);
                    mma16816(acc[mi][ni], ah[mi], b0l, b1l);
                    mma16816(acc[mi][ni], al[mi], b0h, b1h);
                }
            }
        }
        __syncthreads();
    }

    // epilogue
    #pragma unroll
    for (int mi = 0; mi < 2; mi++) {
        int mbase = bm + warpM * 32 + mi * 16 + grp;
        #pragma unroll
        for (int ni = 0; ni < 4; ni++) {
            int n0 = bn + warpN * 32 + ni * 8 + 2 * tig;
            float b0 = bias[n0], b1 = bias[n0 + 1];
            #pragma unroll
            for (int half = 0; half < 2; half++) {
                int m = mbase + half * 8;
                float v0 = acc[mi][ni][half * 2 + 0] + b0;
                float v1 = acc[mi][ni][half * 2 + 1] + b1;
                if (EPI == 0) {
                    Cf[(size_t)m * N + n0]     = v0;
                    Cf[(size_t)m * N + n0 + 1] = v1;
                } else if (EPI == 1) {
                    size_t orow = (size_t)c_map[m];
                    Cf[orow * N + n0]     = v0;
                    Cf[orow * N + n0 + 1] = v1;
                } else if (EPI == 2) {
                    v0 = 0.5f * v0 * (1.0f + erff(v0 * 0.70710678118654752f));
                    v1 = 0.5f * v1 * (1.0f + erff(v1 * 0.70710678118654752f));
                    __nv_bfloat16 h0, l0, h1, l1;
                    split_bf16(v0, h0, l0);
                    split_bf16(v1, h1, l1);
                    Chi[(size_t)m * N + n0]     = h0;
                    Chi[(size_t)m * N + n0 + 1] = h1;
                    Clo[(size_t)m * N + n0]     = l0;
                    Clo[(size_t)m * N + n0 + 1] = l1;
                } else {  // EPI 3: residual
                    v0 += resid[(size_t)m * N + n0];
                    v1 += resid[(size_t)m * N + n0 + 1];
                    Cf[(size_t)m * N + n0]     = v0;
                    Cf[(size_t)m * N + n0 + 1] = v1;
                }
            }
        }
    }
}

// ---------------- windowed attention (writes bf16 hi/lo) ----------------
__global__ __launch_bounds__(256)
void attn_kernel(const float* __restrict__ qkv, const float* __restrict__ mask,
                 const float* __restrict__ rpb,
                 __nv_bfloat16* __restrict__ ohi, __nv_bfloat16* __restrict__ olo)
{
    int w = blockIdx.x;
    int h = blockIdx.y;

    __shared__ float q[NTOK][HD];
    __shared__ float k[NTOK][HD];
    __shared__ float v[NTOK][HD];
    __shared__ float s[NTOK][52];

    int tid = threadIdx.x;
    const float* base = qkv + (long)w * NTOK * (3 * CH) + h * HD;

    for (int idx = tid; idx < NTOK * HD; idx += 256) {
        int t = idx >> 5, d = idx & 31;
        const float* row = base + (long)t * (3 * CH) + d;
        q[t][d] = row[0] * SCALE;
        k[t][d] = row[CH];
        v[t][d] = row[2 * CH];
    }
    __syncthreads();

    int wimg = w & (NWIN - 1);
    const float* mrow = mask + (long)wimg * NTOK * NTOK;
    for (int idx = tid; idx < NTOK * NTOK; idx += 256) {
        int t1 = idx / NTOK, t2 = idx % NTOK;
        float acc = 0.0f;
        #pragma unroll
        for (int d = 0; d < HD; d++) acc += q[t1][d] * k[t2][d];
        int di = (t1 / WS) - (t2 / WS) + (WS - 1);
        int dj = (t1 % WS) - (t2 % WS) + (WS - 1);
        acc += rpb[(di * (2 * WS - 1) + dj) * NHEAD + h];
        acc += mrow[idx];
        s[t1][t2] = acc;
    }
    __syncthreads();

    if (tid < NTOK) {
        float mx = -1e30f;
        #pragma unroll
        for (int j = 0; j < NTOK; j++) mx = fmaxf(mx, s[tid][j]);
        float sum = 0.0f;
        #pragma unroll
        for (int j = 0; j < NTOK; j++) {
            float e = __expf(s[tid][j] - mx);
            s[tid][j] = e;
            sum += e;
        }
        float inv = 1.0f / sum;
        #pragma unroll
        for (int j = 0; j < NTOK; j++) s[tid][j] *= inv;
    }
    __syncthreads();

    long obase = (long)w * NTOK * CH + h * HD;
    for (int idx = tid; idx < NTOK * HD; idx += 256) {
        int t = idx >> 5, d = idx & 31;
        float acc = 0.0f;
        #pragma unroll
        for (int m = 0; m < NTOK; m++) acc += s[t][m] * v[m][d];
        __nv_bfloat16 hh, ll;
        split_bf16(acc, hh, ll);
        ohi[obase + (long)t * CH + d] = hh;
        olo[obase + (long)t * CH + d] = ll;
    }
}

// ---------------- LayerNorm -> bf16 hi/lo ----------------
__global__ __launch_bounds__(128)
void ln_kernel(const float* __restrict__ x, const float* __restrict__ g,
               const float* __restrict__ b,
               __nv_bfloat16* __restrict__ ohi, __nv_bfloat16* __restrict__ olo)
{
    long row = blockIdx.x;
    const float* xr = x + row * CH;
    int tid = threadIdx.x;

    float v0 = xr[tid], v1 = xr[tid + 128], v2 = xr[tid + 256];
    float sum = v0 + v1 + v2;

    __shared__ float red1[4];
    __shared__ float red2[4];
    #pragma unroll
    for (int off = 16; off; off >>= 1) sum += __shfl_xor_sync(0xffffffff, sum, off);
    if ((tid & 31) == 0) red1[tid >> 5] = sum;
    __syncthreads();
    float mu = (red1[0] + red1[1] + red1[2] + red1[3]) * (1.0f / CH);

    float d0 = v0 - mu, d1 = v1 - mu, d2 = v2 - mu;
    float sq = d0 * d0 + d1 * d1 + d2 * d2;
    #pragma unroll
    for (int off = 16; off; off >>= 1) sq += __shfl_xor_sync(0xffffffff, sq, off);
    if ((tid & 31) == 0) red2[tid >> 5] = sq;
    __syncthreads();
    float var = (red2[0] + red2[1] + red2[2] + red2[3]) * (1.0f / CH);
    float rstd = rsqrtf(var + 1e-5f);

    long base = row * CH;
    #pragma unroll
    for (int p = 0; p < 3; p++) {
        int c = tid + p * 128;
        float dv = (p == 0 ? d0 : p == 1 ? d1 : d2);
        float o = dv * rstd * g[c] + b[c];
        __nv_bfloat16 hh, ll;
        split_bf16(o, hh, ll);
        ohi[base + c] = hh;
        olo[base + c] = ll;
    }
}

// ---------------- launch ----------------
extern "C" void kernel_launch(void* const* d_in, const int* in_sizes, int n_in,
                              void* d_out, int out_size)
{
    const float* x      = (const float*)d_in[0];
    const float* mask   = (const float*)d_in[1];
    const float* qkv_w  = (const float*)d_in[2];
    const float* qkv_b  = (const float*)d_in[3];
    const float* proj_w = (const float*)d_in[4];
    const float* proj_b = (const float*)d_in[5];
    const float* rpb    = (const float*)d_in[6];
    const float* n2g    = (const float*)d_in[7];
    const float* n2b    = (const float*)d_in[8];
    const float* fc1w   = (const float*)d_in[9];
    const float* fc1b   = (const float*)d_in[10];
    const float* fc2w   = (const float*)d_in[11];
    const float* fc2b   = (const float*)d_in[12];
    float* out = (float*)d_out;

    void *p;
    #define GSYM(sym, var, ty) cudaGetSymbolAddress(&p, sym); ty* var = (ty*)p;
    GSYM(g_xg_hi, xg_hi, __nv_bfloat16) GSYM(g_xg_lo, xg_lo, __nv_bfloat16)
    GSYM(g_qkv, qkv, float)
    GSYM(g_at_hi, at_hi, __nv_bfloat16) GSYM(g_at_lo, at_lo, __nv_bfloat16)
    GSYM(g_x2, x2, float)
    GSYM(g_hn_hi, hn_hi, __nv_bfloat16) GSYM(g_hn_lo, hn_lo, __nv_bfloat16)
    GSYM(g_hid_hi, hid_hi, __nv_bfloat16) GSYM(g_hid_lo, hid_lo, __nv_bfloat16)
    GSYM(g_map, map, int)
    GSYM(g_wqkv_hi, wqkv_hi, __nv_bfloat16) GSYM(g_wqkv_lo, wqkv_lo, __nv_bfloat16)
    GSYM(g_wprj_hi, wprj_hi, __nv_bfloat16) GSYM(g_wprj_lo, wprj_lo, __nv_bfloat16)
    GSYM(g_wf1_hi, wf1_hi, __nv_bfloat16) GSYM(g_wf1_lo, wf1_lo, __nv_bfloat16)
    GSYM(g_wf2_hi, wf2_hi, __nv_bfloat16) GSYM(g_wf2_lo, wf2_lo, __nv_bfloat16)
    #undef GSYM

    build_maps_kernel<<<(MROWS + 255) / 256, 256>>>(map);

    // operand splits
    long nx = (long)MROWS * CH;
    conv_gather_split<<<(int)((nx + 255) / 256), 256>>>(x, map, xg_hi, xg_lo);
    conv_split<<<(3 * CH * CH + 255) / 256, 256>>>(qkv_w, wqkv_hi, wqkv_lo, 3 * CH * CH);
    conv_split<<<(CH * CH + 255) / 256, 256>>>(proj_w, wprj_hi, wprj_lo, CH * CH);
    conv_split<<<(HID * CH + 255) / 256, 256>>>(fc1w, wf1_hi, wf1_lo, HID * CH);
    conv_split<<<(CH * HID + 255) / 256, 256>>>(fc2w, wf2_hi, wf2_lo, CH * HID);

    // QKV GEMM -> fp32 qkv (windowed order)
    gemm_mma<0><<<dim3((3 * CH) / 64, MROWS / 128), 256>>>(
        xg_hi, xg_lo, wqkv_hi, wqkv_lo, qkv_b, qkv, nullptr, nullptr,
        MROWS, 3 * CH, CH, nullptr, nullptr);

    // attention -> bf16 hi/lo
    attn_kernel<<<dim3(BATCH * NWIN, NHEAD), 256>>>(qkv, mask, rpb, at_hi, at_lo);

    // proj + scatter to image order -> x2
    gemm_mma<1><<<dim3(CH / 64, MROWS / 128), 256>>>(
        at_hi, at_lo, wprj_hi, wprj_lo, proj_b, x2, nullptr, nullptr,
        MROWS, CH, CH, map, nullptr);

    // LayerNorm -> bf16 hi/lo
    ln_kernel<<<MROWS, 128>>>(x2, n2g, n2b, hn_hi, hn_lo);

    // FC1 + GELU -> bf16 hi/lo
    gemm_mma<2><<<dim3(HID / 64, MROWS / 128), 256>>>(
        hn_hi, hn_lo, wf1_hi, wf1_lo, fc1b, nullptr, hid_hi, hid_lo,
        MROWS, HID, CH, nullptr, nullptr);

    // FC2 + residual -> out
    gemm_mma<3><<<dim3(CH / 64, MROWS / 128), 256>>>(
        hid_hi, hid_lo, wf2_hi, wf2_lo, fc2b, out, nullptr, nullptr,
        MROWS, CH, HID, nullptr, x2);
}

// round 5
// speedup vs baseline: 1.7921x; 1.2073x over previous
#include <cuda_runtime.h>
#include <cuda_bf16.h>
#include <math.h>
#include <stdint.h>

// ---------------- problem constants ----------------
#define BATCH 16
#define HW    56
#define CH    384
#define NHEAD 12
#define WS    7
#define NTOK  49
#define HD    32
#define NWIN  64
#define MROWS 50176
#define HID   1536
#define SCALE 0.17677669529663687f

// ---------------- scratch ----------------
__device__ __nv_bfloat16 g_xg_hi[(long)MROWS * CH];
__device__ __nv_bfloat16 g_xg_lo[(long)MROWS * CH];
__device__ float         g_qkv[(long)MROWS * 3 * CH];
__device__ __nv_bfloat16 g_at_hi[(long)MROWS * CH];
__device__ __nv_bfloat16 g_at_lo[(long)MROWS * CH];
__device__ float         g_x2[(long)MROWS * CH];
__device__ __nv_bfloat16 g_hn_hi[(long)MROWS * CH];
__device__ __nv_bfloat16 g_hn_lo[(long)MROWS * CH];
__device__ __nv_bfloat16 g_hid_hi[(long)MROWS * HID];
__device__ __nv_bfloat16 g_hid_lo[(long)MROWS * HID];
__device__ int g_map[MROWS];
__device__ __nv_bfloat16 g_wqkv_hi[3 * CH * CH], g_wqkv_lo[3 * CH * CH];
__device__ __nv_bfloat16 g_wprj_hi[CH * CH],     g_wprj_lo[CH * CH];
__device__ __nv_bfloat16 g_wf1_hi[HID * CH],     g_wf1_lo[HID * CH];
__device__ __nv_bfloat16 g_wf2_hi[CH * HID],     g_wf2_lo[CH * HID];

// ---------------- helpers ----------------
__device__ __forceinline__ uint32_t smem_u32(const void* p) {
    uint32_t a;
    asm("{ .reg .u64 t; cvta.to.shared.u64 t, %1; cvt.u32.u64 %0, t; }" : "=r"(a) : "l"(p));
    return a;
}

#define CP16(dst, src) asm volatile("cp.async.cg.shared.global [%0], [%1], 16;\n" :: "r"(dst), "l"(src))
#define CP_COMMIT()    asm volatile("cp.async.commit_group;\n" ::: "memory")
#define CP_WAIT(n)     asm volatile("cp.async.wait_group %0;\n" :: "n"(n) : "memory")

__device__ __forceinline__ void ldsm4(uint32_t* r, uint32_t addr) {
    asm volatile("ldmatrix.sync.aligned.m8n8.x4.shared.b16 {%0,%1,%2,%3}, [%4];"
                 : "=r"(r[0]), "=r"(r[1]), "=r"(r[2]), "=r"(r[3]) : "r"(addr));
}

__device__ __forceinline__ void mma16816(float* c, const uint32_t* a, uint32_t b0, uint32_t b1) {
    asm volatile(
        "mma.sync.aligned.m16n8k16.row.col.f32.bf16.bf16.f32 "
        "{%0,%1,%2,%3}, {%4,%5,%6,%7}, {%8,%9}, {%0,%1,%2,%3};\n"
        : "+f"(c[0]), "+f"(c[1]), "+f"(c[2]), "+f"(c[3])
        : "r"(a[0]), "r"(a[1]), "r"(a[2]), "r"(a[3]), "r"(b0), "r"(b1));
}

// ---------------- row permutation map ----------------
__global__ void build_maps_kernel(int* __restrict__ map) {
    int r = blockIdx.x * 256 + threadIdx.x;
    if (r >= MROWS) return;
    int w = r / NTOK, t = r % NTOK;
    int b = w / NWIN, wrem = w % NWIN;
    int wi = wrem / 8, wj = wrem % 8;
    int ti = t / WS, tj = t % WS;
    int h0 = (wi * WS + ti + 3) % HW;
    int w0 = (wj * WS + tj + 3) % HW;
    map[r] = b * (HW * HW) + h0 * HW + w0;
}

// ---------------- fp32 -> bf16 hi/lo split ----------------
__device__ __forceinline__ void split_bf16(float v, __nv_bfloat16& h, __nv_bfloat16& l) {
    h = __float2bfloat16(v);
    l = __float2bfloat16(v - __bfloat162float(h));
}

__global__ void conv_split(const float* __restrict__ src,
                           __nv_bfloat16* __restrict__ hi, __nv_bfloat16* __restrict__ lo,
                           long n) {
    long i = (long)blockIdx.x * 256 + threadIdx.x;
    if (i >= n) return;
    __nv_bfloat16 h, l;
    split_bf16(src[i], h, l);
    hi[i] = h; lo[i] = l;
}

__global__ void conv_gather_split(const float* __restrict__ x, const int* __restrict__ map,
                                  __nv_bfloat16* __restrict__ hi, __nv_bfloat16* __restrict__ lo) {
    long i = (long)blockIdx.x * 256 + threadIdx.x;
    if (i >= (long)MROWS * CH) return;
    long r = i / CH, c = i % CH;
    float v = x[(long)map[r] * CH + c];
    __nv_bfloat16 h, l;
    split_bf16(v, h, l);
    hi[i] = h; lo[i] = l;
}

// ---------------- pipelined bf16x3 HMMA GEMM ------------------------------
// C[M,N] = A[M,K] @ W[N,K]^T + bias.  CTA tile 128x128xBK32, 3-stage cp.async.
// 8 warps, warp tile 64(M) x 32(N): warpM = wid&1, warpN = wid>>1.
// Smem rows: 32 bf16 = 64B data, stride 80B -> (row*5+c)%8 distinct -> LDSM ok.
// EPI: 0 fp32, 1 fp32 scatter c_map, 2 GELU->bf16 hi/lo, 3 +resid fp32.

#define RSTRIDE 80
#define TILE_B  (128 * RSTRIDE)            // 10240
#define STAGE_B (4 * TILE_B)               // Ah Al Bh Bl = 40960
#define STAGES  3
#define SMEM_REQ (STAGES * STAGE_B)        // 122880

__device__ __forceinline__ void load_stage(
    uint32_t sbase, const __nv_bfloat16* Ah, const __nv_bfloat16* Al,
    const __nv_bfloat16* Bh, const __nv_bfloat16* Bl, int K, int k0, int tid)
{
    int row = tid >> 1;
    int c0 = (tid & 1) * 2;
    uint32_t so = (uint32_t)(row * RSTRIDE + c0 * 16);
    size_t go = (size_t)row * K + k0 + c0 * 8;
    const char* pa = (const char*)(Ah + go);
    const char* pb = (const char*)(Al + go);
    const char* pc = (const char*)(Bh + go);
    const char* pd = (const char*)(Bl + go);
    CP16(sbase + so,                pa);
    CP16(sbase + so + 16,           pa + 16);
    CP16(sbase + TILE_B + so,       pb);
    CP16(sbase + TILE_B + so + 16,  pb + 16);
    CP16(sbase + 2 * TILE_B + so,      pc);
    CP16(sbase + 2 * TILE_B + so + 16, pc + 16);
    CP16(sbase + 3 * TILE_B + so,      pd);
    CP16(sbase + 3 * TILE_B + so + 16, pd + 16);
}

template <int EPI>
__global__ __launch_bounds__(256, 1)
void gemm_mma(const __nv_bfloat16* __restrict__ Ahi, const __nv_bfloat16* __restrict__ Alo,
              const __nv_bfloat16* __restrict__ Bhi, const __nv_bfloat16* __restrict__ Blo,
              const float* __restrict__ bias,
              float* __restrict__ Cf,
              __nv_bfloat16* __restrict__ Chi, __nv_bfloat16* __restrict__ Clo,
              int M, int N, int K,
              const int* __restrict__ c_map, const float* __restrict__ resid)
{
    extern __shared__ char smem[];
    uint32_t sb = smem_u32(smem);

    int tid = threadIdx.x;
    int wid = tid >> 5, lane = tid & 31;
    int warpM = wid & 1, warpN = wid >> 1;
    int bm = blockIdx.y * 128, bn = blockIdx.x * 128;
    int grp = lane >> 2, tig = lane & 3;

    const __nv_bfloat16* pAh = Ahi + (size_t)bm * K;
    const __nv_bfloat16* pAl = Alo + (size_t)bm * K;
    const __nv_bfloat16* pBh = Bhi + (size_t)bn * K;
    const __nv_bfloat16* pBl = Blo + (size_t)bn * K;

    // ldmatrix lane address offsets (within a tile, before kstep*32 bytes)
    // A x4: quad0 rows r0..7 chunk0, quad1 rows+8 chunk0, quad2 rows chunk1, quad3 rows+8 chunk1
    int a_row = warpM * 64 + (lane & 7) + ((lane >> 3) & 1) * 8;
    uint32_t a_off = (uint32_t)(a_row * RSTRIDE + (lane >> 4) * 16);
    // B x4: quad0 n0..7 chunk0, quad1 n0..7 chunk1, quad2 n+8 chunk0, quad3 n+8 chunk1
    int b_row = warpN * 32 + (lane & 7) + (lane >> 4) * 8;
    uint32_t b_off = (uint32_t)(b_row * RSTRIDE + ((lane >> 3) & 1) * 16);

    float acc[4][4][4];
    #pragma unroll
    for (int a = 0; a < 4; a++)
        #pragma unroll
        for (int b = 0; b < 4; b++)
            #pragma unroll
            for (int c = 0; c < 4; c++) acc[a][b][c] = 0.0f;

    int nk = K / 32;

    // prologue: fill STAGES-1 stages
    #pragma unroll
    for (int s = 0; s < STAGES - 1; s++) {
        if (s < nk) load_stage(sb + s * STAGE_B, pAh, pAl, pBh, pBl, K, s * 32, tid);
        CP_COMMIT();
    }

    for (int k = 0; k < nk; k++) {
        CP_WAIT(STAGES - 2);
        __syncthreads();

        // prefetch stage k + STAGES-1
        int kp = k + STAGES - 1;
        if (kp < nk)
            load_stage(sb + (kp % STAGES) * STAGE_B, pAh, pAl, pBh, pBl, K, kp * 32, tid);
        CP_COMMIT();

        uint32_t st = sb + (k % STAGES) * STAGE_B;
        uint32_t sAh = st, sAl = st + TILE_B, sBh = st + 2 * TILE_B, sBl = st + 3 * TILE_B;

        #pragma unroll
        for (int ks = 0; ks < 2; ks++) {
            uint32_t ko = ks * 32;   // 16 bf16 = 32 bytes
            uint32_t ah[4][4], al[4][4], bh[2][4], bl[2][4];
            #pragma unroll
            for (int mf = 0; mf < 4; mf++) {
                ldsm4(ah[mf], sAh + a_off + (uint32_t)(mf * 16 * RSTRIDE) + ko);
                ldsm4(al[mf], sAl + a_off + (uint32_t)(mf * 16 * RSTRIDE) + ko);
            }
            #pragma unroll
            for (int nfp = 0; nfp < 2; nfp++) {
                ldsm4(bh[nfp], sBh + b_off + (uint32_t)(nfp * 16 * RSTRIDE) + ko);
                ldsm4(bl[nfp], sBl + b_off + (uint32_t)(nfp * 16 * RSTRIDE) + ko);
            }
            #pragma unroll
            for (int mf = 0; mf < 4; mf++) {
                #pragma unroll
                for (int nf = 0; nf < 4; nf++) {
                    uint32_t b0h = bh[nf >> 1][(nf & 1) * 2];
                    uint32_t b1h = bh[nf >> 1][(nf & 1) * 2 + 1];
                    uint32_t b0l = bl[nf >> 1][(nf & 1) * 2];
                    uint32_t b1l = bl[nf >> 1][(nf & 1) * 2 + 1];
                    mma16816(acc[mf][nf], ah[mf], b0h, b1h);
                    mma16816(acc[mf][nf], ah[mf], b0l, b1l);
                    mma16816(acc[mf][nf], al[mf], b0h, b1h);
                }
            }
        }
        __syncthreads();
    }

    // epilogue
    #pragma unroll
    for (int mf = 0; mf < 4; mf++) {
        int mbase = bm + warpM * 64 + mf * 16 + grp;
        #pragma unroll
        for (int nf = 0; nf < 4; nf++) {
            int n0 = bn + warpN * 32 + nf * 8 + 2 * tig;
            float bi0 = bias[n0], bi1 = bias[n0 + 1];
            #pragma unroll
            for (int half = 0; half < 2; half++) {
                int m = mbase + half * 8;
                float v0 = acc[mf][nf][half * 2 + 0] + bi0;
                float v1 = acc[mf][nf][half * 2 + 1] + bi1;
                if (EPI == 0) {
                    Cf[(size_t)m * N + n0]     = v0;
                    Cf[(size_t)m * N + n0 + 1] = v1;
                } else if (EPI == 1) {
                    size_t orow = (size_t)c_map[m];
                    Cf[orow * N + n0]     = v0;
                    Cf[orow * N + n0 + 1] = v1;
                } else if (EPI == 2) {
                    v0 = 0.5f * v0 * (1.0f + erff(v0 * 0.70710678118654752f));
                    v1 = 0.5f * v1 * (1.0f + erff(v1 * 0.70710678118654752f));
                    __nv_bfloat16 h0, l0, h1, l1;
                    split_bf16(v0, h0, l0);
                    split_bf16(v1, h1, l1);
                    __nv_bfloat162 hp, lp;
                    hp.x = h0; hp.y = h1; lp.x = l0; lp.y = l1;
                    *(__nv_bfloat162*)(Chi + (size_t)m * N + n0) = hp;
                    *(__nv_bfloat162*)(Clo + (size_t)m * N + n0) = lp;
                } else {
                    size_t rb = (size_t)m * N + n0;
                    v0 += resid[rb];
                    v1 += resid[rb + 1];
                    Cf[rb]     = v0;
                    Cf[rb + 1] = v1;
                }
            }
        }
    }
}

// ---------------- windowed attention (writes bf16 hi/lo) ----------------
__global__ __launch_bounds__(256)
void attn_kernel(const float* __restrict__ qkv, const float* __restrict__ mask,
                 const float* __restrict__ rpb,
                 __nv_bfloat16* __restrict__ ohi, __nv_bfloat16* __restrict__ olo)
{
    int w = blockIdx.x;
    int h = blockIdx.y;

    __shared__ float q[NTOK][HD];
    __shared__ float k[NTOK][HD];
    __shared__ float v[NTOK][HD];
    __shared__ float s[NTOK][52];

    int tid = threadIdx.x;
    const float* base = qkv + (long)w * NTOK * (3 * CH) + h * HD;

    for (int idx = tid; idx < NTOK * HD; idx += 256) {
        int t = idx >> 5, d = idx & 31;
        const float* row = base + (long)t * (3 * CH) + d;
        q[t][d] = row[0] * SCALE;
        k[t][d] = row[CH];
        v[t][d] = row[2 * CH];
    }
    __syncthreads();

    int wimg = w & (NWIN - 1);
    const float* mrow = mask + (long)wimg * NTOK * NTOK;
    for (int idx = tid; idx < NTOK * NTOK; idx += 256) {
        int t1 = idx / NTOK, t2 = idx % NTOK;
        float acc = 0.0f;
        #pragma unroll
        for (int d = 0; d < HD; d++) acc += q[t1][d] * k[t2][d];
        int di = (t1 / WS) - (t2 / WS) + (WS - 1);
        int dj = (t1 % WS) - (t2 % WS) + (WS - 1);
        acc += rpb[(di * (2 * WS - 1) + dj) * NHEAD + h];
        acc += mrow[idx];
        s[t1][t2] = acc;
    }
    __syncthreads();

    if (tid < NTOK) {
        float mx = -1e30f;
        #pragma unroll
        for (int j = 0; j < NTOK; j++) mx = fmaxf(mx, s[tid][j]);
        float sum = 0.0f;
        #pragma unroll
        for (int j = 0; j < NTOK; j++) {
            float e = __expf(s[tid][j] - mx);
            s[tid][j] = e;
            sum += e;
        }
        float inv = 1.0f / sum;
        #pragma unroll
        for (int j = 0; j < NTOK; j++) s[tid][j] *= inv;
    }
    __syncthreads();

    long obase = (long)w * NTOK * CH + h * HD;
    for (int idx = tid; idx < NTOK * HD; idx += 256) {
        int t = idx >> 5, d = idx & 31;
        float acc = 0.0f;
        #pragma unroll
        for (int m = 0; m < NTOK; m++) acc += s[t][m] * v[m][d];
        __nv_bfloat16 hh, ll;
        split_bf16(acc, hh, ll);
        ohi[obase + (long)t * CH + d] = hh;
        olo[obase + (long)t * CH + d] = ll;
    }
}

// ---------------- LayerNorm -> bf16 hi/lo ----------------
__global__ __launch_bounds__(128)
void ln_kernel(const float* __restrict__ x, const float* __restrict__ g,
               const float* __restrict__ b,
               __nv_bfloat16* __restrict__ ohi, __nv_bfloat16* __restrict__ olo)
{
    long row = blockIdx.x;
    const float* xr = x + row * CH;
    int tid = threadIdx.x;

    float v0 = xr[tid], v1 = xr[tid + 128], v2 = xr[tid + 256];
    float sum = v0 + v1 + v2;

    __shared__ float red1[4];
    __shared__ float red2[4];
    #pragma unroll
    for (int off = 16; off; off >>= 1) sum += __shfl_xor_sync(0xffffffff, sum, off);
    if ((tid & 31) == 0) red1[tid >> 5] = sum;
    __syncthreads();
    float mu = (red1[0] + red1[1] + red1[2] + red1[3]) * (1.0f / CH);

    float d0 = v0 - mu, d1 = v1 - mu, d2 = v2 - mu;
    float sq = d0 * d0 + d1 * d1 + d2 * d2;
    #pragma unroll
    for (int off = 16; off; off >>= 1) sq += __shfl_xor_sync(0xffffffff, sq, off);
    if ((tid & 31) == 0) red2[tid >> 5] = sq;
    __syncthreads();
    float var = (red2[0] + red2[1] + red2[2] + red2[3]) * (1.0f / CH);
    float rstd = rsqrtf(var + 1e-5f);

    long base = row * CH;
    #pragma unroll
    for (int p = 0; p < 3; p++) {
        int c = tid + p * 128;
        float dv = (p == 0 ? d0 : p == 1 ? d1 : d2);
        float o = dv * rstd * g[c] + b[c];
        __nv_bfloat16 hh, ll;
        split_bf16(o, hh, ll);
        ohi[base + c] = hh;
        olo[base + c] = ll;
    }
}

// ---------------- launch ----------------
extern "C" void kernel_launch(void* const* d_in, const int* in_sizes, int n_in,
                              void* d_out, int out_size)
{
    const float* x      = (const float*)d_in[0];
    const float* mask   = (const float*)d_in[1];
    const float* qkv_w  = (const float*)d_in[2];
    const float* qkv_b  = (const float*)d_in[3];
    const float* proj_w = (const float*)d_in[4];
    const float* proj_b = (const float*)d_in[5];
    const float* rpb    = (const float*)d_in[6];
    const float* n2g    = (const float*)d_in[7];
    const float* n2b    = (const float*)d_in[8];
    const float* fc1w   = (const float*)d_in[9];
    const float* fc1b   = (const float*)d_in[10];
    const float* fc2w   = (const float*)d_in[11];
    const float* fc2b   = (const float*)d_in[12];
    float* out = (float*)d_out;

    void *p;
    #define GSYM(sym, var, ty) cudaGetSymbolAddress(&p, sym); ty* var = (ty*)p;
    GSYM(g_xg_hi, xg_hi, __nv_bfloat16) GSYM(g_xg_lo, xg_lo, __nv_bfloat16)
    GSYM(g_qkv, qkv, float)
    GSYM(g_at_hi, at_hi, __nv_bfloat16) GSYM(g_at_lo, at_lo, __nv_bfloat16)
    GSYM(g_x2, x2, float)
    GSYM(g_hn_hi, hn_hi, __nv_bfloat16) GSYM(g_hn_lo, hn_lo, __nv_bfloat16)
    GSYM(g_hid_hi, hid_hi, __nv_bfloat16) GSYM(g_hid_lo, hid_lo, __nv_bfloat16)
    GSYM(g_map, map, int)
    GSYM(g_wqkv_hi, wqkv_hi, __nv_bfloat16) GSYM(g_wqkv_lo, wqkv_lo, __nv_bfloat16)
    GSYM(g_wprj_hi, wprj_hi, __nv_bfloat16) GSYM(g_wprj_lo, wprj_lo, __nv_bfloat16)
    GSYM(g_wf1_hi, wf1_hi, __nv_bfloat16) GSYM(g_wf1_lo, wf1_lo, __nv_bfloat16)
    GSYM(g_wf2_hi, wf2_hi, __nv_bfloat16) GSYM(g_wf2_lo, wf2_lo, __nv_bfloat16)
    #undef GSYM

    cudaFuncSetAttribute(gemm_mma<0>, cudaFuncAttributeMaxDynamicSharedMemorySize, SMEM_REQ);
    cudaFuncSetAttribute(gemm_mma<1>, cudaFuncAttributeMaxDynamicSharedMemorySize, SMEM_REQ);
    cudaFuncSetAttribute(gemm_mma<2>, cudaFuncAttributeMaxDynamicSharedMemorySize, SMEM_REQ);
    cudaFuncSetAttribute(gemm_mma<3>, cudaFuncAttributeMaxDynamicSharedMemorySize, SMEM_REQ);

    build_maps_kernel<<<(MROWS + 255) / 256, 256>>>(map);

    long nx = (long)MROWS * CH;
    conv_gather_split<<<(int)((nx + 255) / 256), 256>>>(x, map, xg_hi, xg_lo);
    conv_split<<<(3 * CH * CH + 255) / 256, 256>>>(qkv_w, wqkv_hi, wqkv_lo, 3 * CH * CH);
    conv_split<<<(CH * CH + 255) / 256, 256>>>(proj_w, wprj_hi, wprj_lo, CH * CH);
    conv_split<<<(HID * CH + 255) / 256, 256>>>(fc1w, wf1_hi, wf1_lo, HID * CH);
    conv_split<<<(CH * HID + 255) / 256, 256>>>(fc2w, wf2_hi, wf2_lo, CH * HID);

    // QKV -> fp32 qkv (windowed order)
    gemm_mma<0><<<dim3((3 * CH) / 128, MROWS / 128), 256, SMEM_REQ>>>(
        xg_hi, xg_lo, wqkv_hi, wqkv_lo, qkv_b, qkv, nullptr, nullptr,
        MROWS, 3 * CH, CH, nullptr, nullptr);

    attn_kernel<<<dim3(BATCH * NWIN, NHEAD), 256>>>(qkv, mask, rpb, at_hi, at_lo);

    // proj + scatter to image order -> x2
    gemm_mma<1><<<dim3(CH / 128, MROWS / 128), 256, SMEM_REQ>>>(
        at_hi, at_lo, wprj_hi, wprj_lo, proj_b, x2, nullptr, nullptr,
        MROWS, CH, CH, map, nullptr);

    ln_kernel<<<MROWS, 128>>>(x2, n2g, n2b, hn_hi, hn_lo);

    // FC1 + GELU -> bf16 hi/lo
    gemm_mma<2><<<dim3(HID / 128, MROWS / 128), 256, SMEM_REQ>>>(
        hn_hi, hn_lo, wf1_hi, wf1_lo, fc1b, nullptr, hid_hi, hid_lo,
        MROWS, HID, CH, nullptr, nullptr);

    // FC2 + residual -> out
    gemm_mma<3><<<dim3(CH / 128, MROWS / 128), 256, SMEM_REQ>>>(
        hid_hi, hid_lo, wf2_hi, wf2_lo, fc2b, out, nullptr, nullptr,
        MROWS, CH, HID, nullptr, x2);
}

// round 6
// speedup vs baseline: 2.1730x; 1.2125x over previous
#include <cuda_runtime.h>
#include <cuda_fp16.h>
#include <math.h>
#include <stdint.h>

// ---------------- problem constants ----------------
#define BATCH 16
#define HW    56
#define CH    384
#define NHEAD 12
#define WS    7
#define NTOK  49
#define HD    32
#define NWIN  64
#define MROWS 50176
#define HID   1536
#define SCALE 0.17677669529663687f

// ---------------- scratch ----------------
__device__ __half g_xg[(long)MROWS * CH];          // gathered x, fp16
__device__ __half g_qkv[(long)MROWS * 3 * CH];     // qkv, fp16, windowed order
__device__ __half g_at[(long)MROWS * CH];          // attention out, fp16
__device__ float  g_x2[(long)MROWS * CH];          // proj out (image order), fp32
__device__ __half g_hn[(long)MROWS * CH];          // LN out, fp16
__device__ __half g_hid[(long)MROWS * HID];        // fc1+gelu out, fp16
__device__ int    g_map[MROWS];
// weight splits (hi + lo fp16)
__device__ __half g_wqkv_hi[3 * CH * CH], g_wqkv_lo[3 * CH * CH];
__device__ __half g_wprj_hi[CH * CH],     g_wprj_lo[CH * CH];
__device__ __half g_wf1_hi[HID * CH],     g_wf1_lo[HID * CH];
__device__ __half g_wf2_hi[CH * HID],     g_wf2_lo[CH * HID];

// ---------------- helpers ----------------
__device__ __forceinline__ uint32_t smem_u32(const void* p) {
    uint32_t a;
    asm("{ .reg .u64 t; cvta.to.shared.u64 t, %1; cvt.u32.u64 %0, t; }" : "=r"(a) : "l"(p));
    return a;
}

#define CP16(dst, src) asm volatile("cp.async.cg.shared.global [%0], [%1], 16;\n" :: "r"(dst), "l"(src))
#define CP_COMMIT()    asm volatile("cp.async.commit_group;\n" ::: "memory")
#define CP_WAIT(n)     asm volatile("cp.async.wait_group %0;\n" :: "n"(n) : "memory")

__device__ __forceinline__ void ldsm4(uint32_t* r, uint32_t addr) {
    asm volatile("ldmatrix.sync.aligned.m8n8.x4.shared.b16 {%0,%1,%2,%3}, [%4];"
                 : "=r"(r[0]), "=r"(r[1]), "=r"(r[2]), "=r"(r[3]) : "r"(addr));
}

__device__ __forceinline__ void mma16816(float* c, const uint32_t* a, uint32_t b0, uint32_t b1) {
    asm volatile(
        "mma.sync.aligned.m16n8k16.row.col.f32.f16.f16.f32 "
        "{%0,%1,%2,%3}, {%4,%5,%6,%7}, {%8,%9}, {%0,%1,%2,%3};\n"
        : "+f"(c[0]), "+f"(c[1]), "+f"(c[2]), "+f"(c[3])
        : "r"(a[0]), "r"(a[1]), "r"(a[2]), "r"(a[3]), "r"(b0), "r"(b1));
}

// ---------------- row permutation map ----------------
__global__ void build_maps_kernel(int* __restrict__ map) {
    int r = blockIdx.x * 256 + threadIdx.x;
    if (r >= MROWS) return;
    int w = r / NTOK, t = r % NTOK;
    int b = w / NWIN, wrem = w % NWIN;
    int wi = wrem / 8, wj = wrem % 8;
    int ti = t / WS, tj = t % WS;
    int h0 = (wi * WS + ti + 3) % HW;
    int w0 = (wj * WS + tj + 3) % HW;
    map[r] = b * (HW * HW) + h0 * HW + w0;
}

// ---------------- conversions ----------------
__device__ __forceinline__ void split_fp16(float v, __half& h, __half& l) {
    h = __float2half(v);
    l = __float2half(v - __half2float(h));
}

__global__ void conv_wsplit(const float* __restrict__ src,
                            __half* __restrict__ hi, __half* __restrict__ lo, long n) {
    long i = (long)blockIdx.x * 256 + threadIdx.x;
    if (i >= n) return;
    __half h, l;
    split_fp16(src[i], h, l);
    hi[i] = h; lo[i] = l;
}

__global__ void conv_gather(const float* __restrict__ x, const int* __restrict__ map,
                            __half* __restrict__ o) {
    long i = (long)blockIdx.x * 256 + threadIdx.x;
    if (i >= (long)MROWS * CH) return;
    long r = i / CH, c = i % CH;
    o[i] = __float2half(x[(long)map[r] * CH + c]);
}

// ---------------- pipelined fp16x2 HMMA GEMM ------------------------------
// C[M,N] = A[M,K] @ (Wh+Wl)[N,K]^T + bias.  CTA tile 128x128xBK32,
// 4-stage cp.async.  8 warps, warp tile 64(M) x 32(N).
// smem rows: 32 fp16 = 64B data, stride 80B -> LDSM conflict-free.
// EPI: 0 -> fp16 out, 1 -> fp32 scatter via c_map, 2 -> GELU -> fp16 out,
//      3 -> +resid -> fp32 out.

#define RSTRIDE 80
#define TILE_B  (128 * RSTRIDE)            // 10240
#define STAGE_B (3 * TILE_B)               // A, Bh, Bl = 30720
#define STAGES  4
#define SMEM_REQ (STAGES * STAGE_B)        // 122880

__device__ __forceinline__ void load_stage(
    uint32_t sbase, const __half* A, const __half* Bh, const __half* Bl,
    int K, int k0, int tid)
{
    int row = tid >> 1;
    int c0 = (tid & 1) * 2;
    uint32_t so = (uint32_t)(row * RSTRIDE + c0 * 16);
    size_t go = (size_t)row * K + k0 + c0 * 8;
    const char* pa = (const char*)(A + go);
    const char* pb = (const char*)(Bh + go);
    const char* pc = (const char*)(Bl + go);
    CP16(sbase + so,                    pa);
    CP16(sbase + so + 16,               pa + 16);
    CP16(sbase + TILE_B + so,           pb);
    CP16(sbase + TILE_B + so + 16,      pb + 16);
    CP16(sbase + 2 * TILE_B + so,       pc);
    CP16(sbase + 2 * TILE_B + so + 16,  pc + 16);
}

template <int EPI>
__global__ __launch_bounds__(256, 1)
void gemm_mma(const __half* __restrict__ A,
              const __half* __restrict__ Bhw, const __half* __restrict__ Blw,
              const float* __restrict__ bias,
              float* __restrict__ Cf, __half* __restrict__ Ch,
              int M, int N, int K,
              const int* __restrict__ c_map, const float* __restrict__ resid)
{
    extern __shared__ char smem[];
    uint32_t sb = smem_u32(smem);

    int tid = threadIdx.x;
    int wid = tid >> 5, lane = tid & 31;
    int warpM = wid & 1, warpN = wid >> 1;
    int bm = blockIdx.y * 128, bn = blockIdx.x * 128;
    int grp = lane >> 2, tig = lane & 3;

    const __half* pA  = A   + (size_t)bm * K;
    const __half* pBh = Bhw + (size_t)bn * K;
    const __half* pBl = Blw + (size_t)bn * K;

    int a_row = warpM * 64 + (lane & 7) + ((lane >> 3) & 1) * 8;
    uint32_t a_off = (uint32_t)(a_row * RSTRIDE + (lane >> 4) * 16);
    int b_row = warpN * 32 + (lane & 7) + (lane >> 4) * 8;
    uint32_t b_off = (uint32_t)(b_row * RSTRIDE + ((lane >> 3) & 1) * 16);

    float acc[4][4][4];
    #pragma unroll
    for (int a = 0; a < 4; a++)
        #pragma unroll
        for (int b = 0; b < 4; b++)
            #pragma unroll
            for (int c = 0; c < 4; c++) acc[a][b][c] = 0.0f;

    int nk = K / 32;

    #pragma unroll
    for (int s = 0; s < STAGES - 1; s++) {
        if (s < nk) load_stage(sb + s * STAGE_B, pA, pBh, pBl, K, s * 32, tid);
        CP_COMMIT();
    }

    for (int k = 0; k < nk; k++) {
        CP_WAIT(STAGES - 2);
        __syncthreads();

        int kp = k + STAGES - 1;
        if (kp < nk)
            load_stage(sb + (kp % STAGES) * STAGE_B, pA, pBh, pBl, K, kp * 32, tid);
        CP_COMMIT();

        uint32_t st = sb + (k % STAGES) * STAGE_B;
        uint32_t sA = st, sBh = st + TILE_B, sBl = st + 2 * TILE_B;

        #pragma unroll
        for (int ks = 0; ks < 2; ks++) {
            uint32_t ko = ks * 32;
            uint32_t af[4][4], bh[2][4], bl[2][4];
            #pragma unroll
            for (int mf = 0; mf < 4; mf++)
                ldsm4(af[mf], sA + a_off + (uint32_t)(mf * 16 * RSTRIDE) + ko);
            #pragma unroll
            for (int nfp = 0; nfp < 2; nfp++) {
                ldsm4(bh[nfp], sBh + b_off + (uint32_t)(nfp * 16 * RSTRIDE) + ko);
                ldsm4(bl[nfp], sBl + b_off + (uint32_t)(nfp * 16 * RSTRIDE) + ko);
            }
            #pragma unroll
            for (int mf = 0; mf < 4; mf++) {
                #pragma unroll
                for (int nf = 0; nf < 4; nf++) {
                    uint32_t b0h = bh[nf >> 1][(nf & 1) * 2];
                    uint32_t b1h = bh[nf >> 1][(nf & 1) * 2 + 1];
                    uint32_t b0l = bl[nf >> 1][(nf & 1) * 2];
                    uint32_t b1l = bl[nf >> 1][(nf & 1) * 2 + 1];
                    mma16816(acc[mf][nf], af[mf], b0h, b1h);
                    mma16816(acc[mf][nf], af[mf], b0l, b1l);
                }
            }
        }
        __syncthreads();
    }

    // epilogue
    #pragma unroll
    for (int mf = 0; mf < 4; mf++) {
        int mbase = bm + warpM * 64 + mf * 16 + grp;
        #pragma unroll
        for (int nf = 0; nf < 4; nf++) {
            int n0 = bn + warpN * 32 + nf * 8 + 2 * tig;
            float bi0 = bias[n0], bi1 = bias[n0 + 1];
            #pragma unroll
            for (int half_ = 0; half_ < 2; half_++) {
                int m = mbase + half_ * 8;
                float v0 = acc[mf][nf][half_ * 2 + 0] + bi0;
                float v1 = acc[mf][nf][half_ * 2 + 1] + bi1;
                if (EPI == 0) {
                    __half2 hp;
                    hp.x = __float2half(v0); hp.y = __float2half(v1);
                    *(__half2*)(Ch + (size_t)m * N + n0) = hp;
                } else if (EPI == 1) {
                    size_t orow = (size_t)c_map[m];
                    Cf[orow * N + n0]     = v0;
                    Cf[orow * N + n0 + 1] = v1;
                } else if (EPI == 2) {
                    v0 = 0.5f * v0 * (1.0f + erff(v0 * 0.70710678118654752f));
                    v1 = 0.5f * v1 * (1.0f + erff(v1 * 0.70710678118654752f));
                    __half2 hp;
                    hp.x = __float2half(v0); hp.y = __float2half(v1);
                    *(__half2*)(Ch + (size_t)m * N + n0) = hp;
                } else {
                    size_t rb = (size_t)m * N + n0;
                    Cf[rb]     = v0 + resid[rb];
                    Cf[rb + 1] = v1 + resid[rb + 1];
                }
            }
        }
    }
}

// ---------------- windowed attention (fp16 in, fp16 out) ----------------
__global__ __launch_bounds__(256)
void attn_kernel(const __half* __restrict__ qkv, const float* __restrict__ mask,
                 const float* __restrict__ rpb, __half* __restrict__ o)
{
    int w = blockIdx.x;
    int h = blockIdx.y;

    __shared__ float q[NTOK][HD];
    __shared__ float k[NTOK][HD];
    __shared__ float v[NTOK][HD];
    __shared__ float s[NTOK][52];

    int tid = threadIdx.x;
    const __half* base = qkv + (long)w * NTOK * (3 * CH) + h * HD;

    // 49 * 16 half2 loads per q/k/v
    for (int idx = tid; idx < NTOK * (HD / 2); idx += 256) {
        int t = idx >> 4, d2 = idx & 15;
        const __half2* row = (const __half2*)(base + (long)t * (3 * CH)) + d2;
        float2 qv = __half22float2(row[0]);
        float2 kv = __half22float2(row[CH / 2]);
        float2 vv = __half22float2(row[CH]);
        q[t][d2 * 2]     = qv.x * SCALE;
        q[t][d2 * 2 + 1] = qv.y * SCALE;
        k[t][d2 * 2]     = kv.x;
        k[t][d2 * 2 + 1] = kv.y;
        v[t][d2 * 2]     = vv.x;
        v[t][d2 * 2 + 1] = vv.y;
    }
    __syncthreads();

    int wimg = w & (NWIN - 1);
    const float* mrow = mask + (long)wimg * NTOK * NTOK;
    for (int idx = tid; idx < NTOK * NTOK; idx += 256) {
        int t1 = idx / NTOK, t2 = idx % NTOK;
        float acc = 0.0f;
        #pragma unroll
        for (int d = 0; d < HD; d++) acc += q[t1][d] * k[t2][d];
        int di = (t1 / WS) - (t2 / WS) + (WS - 1);
        int dj = (t1 % WS) - (t2 % WS) + (WS - 1);
        acc += rpb[(di * (2 * WS - 1) + dj) * NHEAD + h];
        acc += mrow[idx];
        s[t1][t2] = acc;
    }
    __syncthreads();

    if (tid < NTOK) {
        float mx = -1e30f;
        #pragma unroll
        for (int j = 0; j < NTOK; j++) mx = fmaxf(mx, s[tid][j]);
        float sum = 0.0f;
        #pragma unroll
        for (int j = 0; j < NTOK; j++) {
            float e = __expf(s[tid][j] - mx);
            s[tid][j] = e;
            sum += e;
        }
        float inv = 1.0f / sum;
        #pragma unroll
        for (int j = 0; j < NTOK; j++) s[tid][j] *= inv;
    }
    __syncthreads();

    __half* ob = o + (long)w * NTOK * CH + h * HD;
    for (int idx = tid; idx < NTOK * (HD / 2); idx += 256) {
        int t = idx >> 4, d2 = idx & 15;
        int d = d2 * 2;
        float a0 = 0.0f, a1 = 0.0f;
        #pragma unroll
        for (int m = 0; m < NTOK; m++) {
            float sm = s[t][m];
            a0 += sm * v[m][d];
            a1 += sm * v[m][d + 1];
        }
        __half2 hp;
        hp.x = __float2half(a0); hp.y = __float2half(a1);
        *(__half2*)(ob + (long)t * CH + d) = hp;
    }
}

// ---------------- LayerNorm -> fp16 ----------------
__global__ __launch_bounds__(128)
void ln_kernel(const float* __restrict__ x, const float* __restrict__ g,
               const float* __restrict__ b, __half* __restrict__ o)
{
    long row = blockIdx.x;
    const float* xr = x + row * CH;
    int tid = threadIdx.x;

    float v0 = xr[tid], v1 = xr[tid + 128], v2 = xr[tid + 256];
    float sum = v0 + v1 + v2;

    __shared__ float red1[4];
    __shared__ float red2[4];
    #pragma unroll
    for (int off = 16; off; off >>= 1) sum += __shfl_xor_sync(0xffffffff, sum, off);
    if ((tid & 31) == 0) red1[tid >> 5] = sum;
    __syncthreads();
    float mu = (red1[0] + red1[1] + red1[2] + red1[3]) * (1.0f / CH);

    float d0 = v0 - mu, d1 = v1 - mu, d2 = v2 - mu;
    float sq = d0 * d0 + d1 * d1 + d2 * d2;
    #pragma unroll
    for (int off = 16; off; off >>= 1) sq += __shfl_xor_sync(0xffffffff, sq, off);
    if ((tid & 31) == 0) red2[tid >> 5] = sq;
    __syncthreads();
    float var = (red2[0] + red2[1] + red2[2] + red2[3]) * (1.0f / CH);
    float rstd = rsqrtf(var + 1e-5f);

    long base = row * CH;
    o[base + tid]       = __float2half(d0 * rstd * g[tid]       + b[tid]);
    o[base + tid + 128] = __float2half(d1 * rstd * g[tid + 128] + b[tid + 128]);
    o[base + tid + 256] = __float2half(d2 * rstd * g[tid + 256] + b[tid + 256]);
}

// ---------------- launch ----------------
extern "C" void kernel_launch(void* const* d_in, const int* in_sizes, int n_in,
                              void* d_out, int out_size)
{
    const float* x      = (const float*)d_in[0];
    const float* mask   = (const float*)d_in[1];
    const float* qkv_w  = (const float*)d_in[2];
    const float* qkv_b  = (const float*)d_in[3];
    const float* proj_w = (const float*)d_in[4];
    const float* proj_b = (const float*)d_in[5];
    const float* rpb    = (const float*)d_in[6];
    const float* n2g    = (const float*)d_in[7];
    const float* n2b    = (const float*)d_in[8];
    const float* fc1w   = (const float*)d_in[9];
    const float* fc1b   = (const float*)d_in[10];
    const float* fc2w   = (const float*)d_in[11];
    const float* fc2b   = (const float*)d_in[12];
    float* out = (float*)d_out;

    void *p;
    #define GSYM(sym, var, ty) cudaGetSymbolAddress(&p, sym); ty* var = (ty*)p;
    GSYM(g_xg, xg, __half)
    GSYM(g_qkv, qkv, __half)
    GSYM(g_at, at, __half)
    GSYM(g_x2, x2, float)
    GSYM(g_hn, hn, __half)
    GSYM(g_hid, hid, __half)
    GSYM(g_map, map, int)
    GSYM(g_wqkv_hi, wqkv_hi, __half) GSYM(g_wqkv_lo, wqkv_lo, __half)
    GSYM(g_wprj_hi, wprj_hi, __half) GSYM(g_wprj_lo, wprj_lo, __half)
    GSYM(g_wf1_hi, wf1_hi, __half) GSYM(g_wf1_lo, wf1_lo, __half)
    GSYM(g_wf2_hi, wf2_hi, __half) GSYM(g_wf2_lo, wf2_lo, __half)
    #undef GSYM

    cudaFuncSetAttribute(gemm_mma<0>, cudaFuncAttributeMaxDynamicSharedMemorySize, SMEM_REQ);
    cudaFuncSetAttribute(gemm_mma<1>, cudaFuncAttributeMaxDynamicSharedMemorySize, SMEM_REQ);
    cudaFuncSetAttribute(gemm_mma<2>, cudaFuncAttributeMaxDynamicSharedMemorySize, SMEM_REQ);
    cudaFuncSetAttribute(gemm_mma<3>, cudaFuncAttributeMaxDynamicSharedMemorySize, SMEM_REQ);

    build_maps_kernel<<<(MROWS + 255) / 256, 256>>>(map);

    long nx = (long)MROWS * CH;
    conv_gather<<<(int)((nx + 255) / 256), 256>>>(x, map, xg);
    conv_wsplit<<<(3 * CH * CH + 255) / 256, 256>>>(qkv_w, wqkv_hi, wqkv_lo, 3 * CH * CH);
    conv_wsplit<<<(CH * CH + 255) / 256, 256>>>(proj_w, wprj_hi, wprj_lo, CH * CH);
    conv_wsplit<<<(HID * CH + 255) / 256, 256>>>(fc1w, wf1_hi, wf1_lo, HID * CH);
    conv_wsplit<<<(CH * HID + 255) / 256, 256>>>(fc2w, wf2_hi, wf2_lo, CH * HID);

    // QKV -> fp16 qkv (windowed order)
    gemm_mma<0><<<dim3((3 * CH) / 128, MROWS / 128), 256, SMEM_REQ>>>(
        xg, wqkv_hi, wqkv_lo, qkv_b, nullptr, qkv,
        MROWS, 3 * CH, CH, nullptr, nullptr);

    attn_kernel<<<dim3(BATCH * NWIN, NHEAD), 256>>>(qkv, mask, rpb, at);

    // proj + scatter to image order -> x2 (fp32)
    gemm_mma<1><<<dim3(CH / 128, MROWS / 128), 256, SMEM_REQ>>>(
        at, wprj_hi, wprj_lo, proj_b, x2, nullptr,
        MROWS, CH, CH, map, nullptr);

    ln_kernel<<<MROWS, 128>>>(x2, n2g, n2b, hn);

    // FC1 + GELU -> fp16
    gemm_mma<2><<<dim3(HID / 128, MROWS / 128), 256, SMEM_REQ>>>(
        hn, wf1_hi, wf1_lo, fc1b, nullptr, hid,
        MROWS, HID, CH, nullptr, nullptr);

    // FC2 + residual -> out (fp32)
    gemm_mma<3><<<dim3(CH / 128, MROWS / 128), 256, SMEM_REQ>>>(
        hid, wf2_hi, wf2_lo, fc2b, out, nullptr,
        MROWS, CH, HID, nullptr, x2);
}